// round 2
// baseline (speedup 1.0000x reference)
#include <cuda_runtime.h>
#include <cuda_bf16.h>
#include <cstdint>

using bf16 = __nv_bfloat16;

#define DEVINLINE __device__ __forceinline__

static constexpr int CH    = 512;
static constexpr int HWDIM = 1024;
static constexpr int BATCH = 32;
static constexpr int NALL  = BATCH * HWDIM;   // 32768

// ---------------- scratch (device globals; no allocation allowed) -----------
__device__ bf16  g_W [4 * CH * CH];                    // Wq,Wk,Wv,Wo bf16
__device__ bf16  g_XT[(size_t)NALL * CH];              // x transposed [b*HW+s][c]
__device__ bf16  g_QT[(size_t)NALL * CH];              // [b*HW+s][c]
__device__ bf16  g_KT[(size_t)NALL * CH];              // [b*HW+s][c]
__device__ bf16  g_V [(size_t)CH * NALL];              // [c][b*HW+s]
__device__ float g_S [(size_t)BATCH * HWDIM * HWDIM];  // scores fp32
__device__ bf16  g_P [(size_t)BATCH * HWDIM * HWDIM];  // probs bf16
__device__ bf16  g_HT[(size_t)NALL * CH];              // [b*HW+s][c]

// ---------------- small helpers ---------------------------------------------
DEVINLINE void ldsm4(uint32_t& r0, uint32_t& r1, uint32_t& r2, uint32_t& r3,
                     const bf16* p) {
    uint32_t addr = (uint32_t)__cvta_generic_to_shared(p);
    asm volatile("ldmatrix.sync.aligned.m8n8.x4.shared.b16 {%0,%1,%2,%3}, [%4];"
                 : "=r"(r0), "=r"(r1), "=r"(r2), "=r"(r3) : "r"(addr));
}

DEVINLINE void mma_bf16(float c[4], const uint32_t a[4], const uint32_t b[2]) {
    asm volatile("mma.sync.aligned.m16n8k16.row.col.f32.bf16.bf16.f32 "
                 "{%0,%1,%2,%3},{%4,%5,%6,%7},{%8,%9},{%0,%1,%2,%3};"
                 : "+f"(c[0]), "+f"(c[1]), "+f"(c[2]), "+f"(c[3])
                 : "r"(a[0]), "r"(a[1]), "r"(a[2]), "r"(a[3]),
                   "r"(b[0]), "r"(b[1]));
}

// ---------------- prep kernels -----------------------------------------------
__global__ void convert_w_kernel(const float* __restrict__ wq,
                                 const float* __restrict__ wk,
                                 const float* __restrict__ wv,
                                 const float* __restrict__ wo,
                                 bf16* __restrict__ W) {
    int i = blockIdx.x * blockDim.x + threadIdx.x;
    W[i]               = __float2bfloat16(wq[i]);
    W[i + CH * CH]     = __float2bfloat16(wk[i]);
    W[i + 2 * CH * CH] = __float2bfloat16(wv[i]);
    W[i + 3 * CH * CH] = __float2bfloat16(wo[i]);
}

// x [B][C][HW] fp32 -> XT [B*HW][C] bf16 (tiled transpose, coalesced both ways)
__global__ void xt_kernel(const float* __restrict__ x, bf16* __restrict__ XT) {
    __shared__ float tile[32][33];
    const int b  = blockIdx.z;
    const int s0 = blockIdx.x * 32;
    const int c0 = blockIdx.y * 32;
    const int tx = threadIdx.x, ty = threadIdx.y;
    tile[ty][tx] = x[((size_t)b * CH + c0 + ty) * HWDIM + s0 + tx];
    __syncthreads();
    XT[((size_t)b * HWDIM + s0 + ty) * CH + c0 + tx] = __float2bfloat16(tile[tx][ty]);
}

// ---------------- softmax: one block per row of S ----------------------------
__global__ void softmax_kernel(const float* __restrict__ S, bf16* __restrict__ P) {
    const size_t row = blockIdx.x;
    const int tid = threadIdx.x;
    const int lane = tid & 31, warp = tid >> 5;
    float4 v = ((const float4*)(S + row * HWDIM))[tid];
    float mx = fmaxf(fmaxf(v.x, v.y), fmaxf(v.z, v.w));
    #pragma unroll
    for (int o = 16; o > 0; o >>= 1) mx = fmaxf(mx, __shfl_xor_sync(0xffffffffu, mx, o));
    __shared__ float smax[8], ssum[8];
    if (lane == 0) smax[warp] = mx;
    __syncthreads();
    float m = smax[0];
    #pragma unroll
    for (int i = 1; i < 8; i++) m = fmaxf(m, smax[i]);
    float e0 = __expf(v.x - m), e1 = __expf(v.y - m);
    float e2 = __expf(v.z - m), e3 = __expf(v.w - m);
    float s = e0 + e1 + e2 + e3;
    #pragma unroll
    for (int o = 16; o > 0; o >>= 1) s += __shfl_xor_sync(0xffffffffu, s, o);
    if (lane == 0) ssum[warp] = s;
    __syncthreads();
    float tot = 0.f;
    #pragma unroll
    for (int i = 0; i < 8; i++) tot += ssum[i];
    const float inv = 1.f / tot;
    __nv_bfloat162* p2 = (__nv_bfloat162*)(P + row * HWDIM);
    p2[2 * tid]     = __floats2bfloat162_rn(e0 * inv, e1 * inv);
    p2[2 * tid + 1] = __floats2bfloat162_rn(e2 * inv, e3 * inv);
}

// ---------------- generic bf16 MMA GEMM: C[m,n] = sum_k A[m,k] * B[n,k] ------
// A: [M][K] k-major (lda), B: [N][K] k-major (ldb). Requires M,N % 128 == 0,
// K % 32 == 0 (always true here).
// EPI 0: bf16 out, optional per-col bias
// EPI 1: bf16 out, per-row bias
// EPI 2: fp32 out, * scale
// EPI 3: fp32 out at [b][m][s] (n = b*1024+s) with per-row bias + residual x
template<int EPI>
__global__ void __launch_bounds__(256)
gemm_kernel(const bf16* __restrict__ A, const bf16* __restrict__ B,
            void* __restrict__ Cout,
            int M, int N, int K, int lda, int ldb, int ldc,
            size_t sA_batch, size_t sB_batch, size_t sC_batch,
            const float* __restrict__ bias,
            const float* __restrict__ resid,
            float scale)
{
    constexpr int BM = 128, BN = 128, BK = 32;
    constexpr int LDS = BK + 8;   // +8 half skew -> conflict-free ldmatrix
    __shared__ bf16 shA[2][BM * LDS];
    __shared__ bf16 shB[2][BN * LDS];

    const int tid  = threadIdx.x;
    const int lane = tid & 31;
    const int warp = tid >> 5;
    const int wm   = warp >> 2;   // 0..1 -> 64 rows each
    const int wn   = warp & 3;    // 0..3 -> 32 cols each
    const int bm0  = blockIdx.y * BM;
    const int bn0  = blockIdx.x * BN;
    const int z    = blockIdx.z;

    const bf16* Ab = A + (size_t)z * sA_batch;
    const bf16* Bb = B + (size_t)z * sB_batch;

    const int grow = tid >> 2;        // 0..63
    const int gcol = (tid & 3) * 8;   // 0,8,16,24

    const bf16* gA0 = Ab + (size_t)(bm0 + grow) * lda + gcol;
    const bf16* gA1 = Ab + (size_t)(bm0 + grow + 64) * lda + gcol;
    const bf16* gB0 = Bb + (size_t)(bn0 + grow) * ldb + gcol;
    const bf16* gB1 = Bb + (size_t)(bn0 + grow + 64) * ldb + gcol;

    const int sidx0 = grow * LDS + gcol;
    const int sidx1 = (grow + 64) * LDS + gcol;

    float acc[4][4][4];
    #pragma unroll
    for (int i = 0; i < 4; i++)
        #pragma unroll
        for (int j = 0; j < 4; j++)
            #pragma unroll
            for (int l = 0; l < 4; l++) acc[i][j][l] = 0.f;

    const int nk = K / BK;

    *(uint4*)&shA[0][sidx0] = *(const uint4*)gA0;
    *(uint4*)&shA[0][sidx1] = *(const uint4*)gA1;
    *(uint4*)&shB[0][sidx0] = *(const uint4*)gB0;
    *(uint4*)&shB[0][sidx1] = *(const uint4*)gB1;
    __syncthreads();

    // ldmatrix base offsets (halves), within one buffer
    const int a_off = (wm * 64 + (lane & 15)) * LDS + (lane >> 4) * 8;
    const int b_off = (wn * 32 + (lane & 7) + ((lane >> 4) & 1) * 8) * LDS
                    + ((lane >> 3) & 1) * 8;

    for (int kt = 0; kt < nk; ++kt) {
        const int cur = kt & 1;
        uint4 ra0, ra1, rb0, rb1;
        const bool pf = (kt + 1 < nk);
        if (pf) {
            const size_t o = (size_t)(kt + 1) * BK;
            ra0 = *(const uint4*)(gA0 + o);
            ra1 = *(const uint4*)(gA1 + o);
            rb0 = *(const uint4*)(gB0 + o);
            rb1 = *(const uint4*)(gB1 + o);
        }

        #pragma unroll
        for (int ks = 0; ks < 2; ++ks) {
            uint32_t af[4][4];
            #pragma unroll
            for (int mf = 0; mf < 4; ++mf) {
                const bf16* p = &shA[cur][a_off + mf * 16 * LDS + ks * 16];
                ldsm4(af[mf][0], af[mf][1], af[mf][2], af[mf][3], p);
            }
            uint32_t bfg[4][2];
            #pragma unroll
            for (int pr = 0; pr < 2; ++pr) {
                const bf16* p = &shB[cur][b_off + pr * 16 * LDS + ks * 16];
                ldsm4(bfg[2 * pr][0], bfg[2 * pr][1],
                      bfg[2 * pr + 1][0], bfg[2 * pr + 1][1], p);
            }
            #pragma unroll
            for (int mf = 0; mf < 4; ++mf)
                #pragma unroll
                for (int nf = 0; nf < 4; ++nf)
                    mma_bf16(acc[mf][nf], af[mf], bfg[nf]);
        }

        if (pf) {
            const int nxt = cur ^ 1;
            *(uint4*)&shA[nxt][sidx0] = ra0;
            *(uint4*)&shA[nxt][sidx1] = ra1;
            *(uint4*)&shB[nxt][sidx0] = rb0;
            *(uint4*)&shB[nxt][sidx1] = rb1;
        }
        __syncthreads();
    }

    const int r_base = bm0 + wm * 64 + (lane >> 2);
    const int c_base = bn0 + wn * 32 + ((lane & 3) << 1);

    if (EPI == 0 || EPI == 1) {
        bf16* outp = (bf16*)Cout + (size_t)z * sC_batch;
        #pragma unroll
        for (int mf = 0; mf < 4; ++mf) {
            #pragma unroll
            for (int nf = 0; nf < 4; ++nf) {
                const int r = r_base + mf * 16;
                const int c = c_base + nf * 8;
                float b0 = 0.f, b1 = 0.f, rb0 = 0.f, rb1 = 0.f;
                if (EPI == 0) {
                    if (bias) { b0 = bias[c]; b1 = bias[c + 1]; }
                } else {
                    if (bias) { rb0 = bias[r]; rb1 = bias[r + 8]; }
                }
                const float* a4 = acc[mf][nf];
                __nv_bfloat162 h0 = __floats2bfloat162_rn(a4[0] + b0 + rb0,
                                                          a4[1] + b1 + rb0);
                __nv_bfloat162 h1 = __floats2bfloat162_rn(a4[2] + b0 + rb1,
                                                          a4[3] + b1 + rb1);
                *(__nv_bfloat162*)(outp + (size_t)r * ldc + c)       = h0;
                *(__nv_bfloat162*)(outp + (size_t)(r + 8) * ldc + c) = h1;
            }
        }
    } else if (EPI == 2) {
        float* outp = (float*)Cout + (size_t)z * sC_batch;
        #pragma unroll
        for (int mf = 0; mf < 4; ++mf) {
            #pragma unroll
            for (int nf = 0; nf < 4; ++nf) {
                const int r = r_base + mf * 16;
                const int c = c_base + nf * 8;
                const float* a4 = acc[mf][nf];
                *(float2*)(outp + (size_t)r * ldc + c) =
                    make_float2(a4[0] * scale, a4[1] * scale);
                *(float2*)(outp + (size_t)(r + 8) * ldc + c) =
                    make_float2(a4[2] * scale, a4[3] * scale);
            }
        }
    } else {   // EPI == 3 : final output with residual
        float* outp = (float*)Cout;
        #pragma unroll
        for (int mf = 0; mf < 4; ++mf) {
            #pragma unroll
            for (int nf = 0; nf < 4; ++nf) {
                const int r = r_base + mf * 16;          // output channel o
                const int c = c_base + nf * 8;           // global n = b*HW + s
                const int bb = c >> 10;
                const int s  = c & 1023;
                const size_t i0 = (size_t)bb * (CH * HWDIM) + (size_t)r * HWDIM + s;
                const size_t i1 = i0 + 8 * HWDIM;
                const float br0 = bias ? bias[r] : 0.f;
                const float br1 = bias ? bias[r + 8] : 0.f;
                const float* a4 = acc[mf][nf];
                const float2 x0 = *(const float2*)(resid + i0);
                const float2 x1 = *(const float2*)(resid + i1);
                *(float2*)(outp + i0) = make_float2(a4[0] + br0 + x0.x,
                                                    a4[1] + br0 + x0.y);
                *(float2*)(outp + i1) = make_float2(a4[2] + br1 + x1.x,
                                                    a4[3] + br1 + x1.y);
            }
        }
    }
}

// ---------------- launch ------------------------------------------------------
extern "C" void kernel_launch(void* const* d_in, const int* in_sizes, int n_in,
                              void* d_out, int out_size)
{
    (void)in_sizes; (void)n_in; (void)out_size;
    const float* x  = (const float*)d_in[0];
    const float* Wq = (const float*)d_in[1];
    const float* bq = (const float*)d_in[2];
    const float* Wk = (const float*)d_in[3];
    const float* bk = (const float*)d_in[4];
    const float* Wv = (const float*)d_in[5];
    const float* bv = (const float*)d_in[6];
    const float* Wo = (const float*)d_in[7];
    const float* bo = (const float*)d_in[8];
    float* out = (float*)d_out;

    bf16 *pW, *pXT, *pQT, *pKT, *pV, *pP, *pHT;
    float* pS;
    cudaGetSymbolAddress((void**)&pW,  g_W);
    cudaGetSymbolAddress((void**)&pXT, g_XT);
    cudaGetSymbolAddress((void**)&pQT, g_QT);
    cudaGetSymbolAddress((void**)&pKT, g_KT);
    cudaGetSymbolAddress((void**)&pV,  g_V);
    cudaGetSymbolAddress((void**)&pS,  g_S);
    cudaGetSymbolAddress((void**)&pP,  g_P);
    cudaGetSymbolAddress((void**)&pHT, g_HT);

    // prep
    convert_w_kernel<<<(CH * CH) / 256, 256>>>(Wq, Wk, Wv, Wo, pW);
    xt_kernel<<<dim3(HWDIM / 32, CH / 32, BATCH), dim3(32, 32)>>>(x, pXT);

    // QT = XT * Wq^T  (+bq over cols), KT likewise
    gemm_kernel<0><<<dim3(CH / 128, NALL / 128, 1), 256>>>(
        pXT, pW, pQT, NALL, CH, CH, CH, CH, CH, 0, 0, 0, bq, nullptr, 1.f);
    gemm_kernel<0><<<dim3(CH / 128, NALL / 128, 1), 256>>>(
        pXT, pW + CH * CH, pKT, NALL, CH, CH, CH, CH, CH, 0, 0, 0, bk, nullptr, 1.f);

    // V = Wv * X (+bv over rows), layout [c][b*HW+s]
    gemm_kernel<1><<<dim3(NALL / 128, CH / 128, 1), 256>>>(
        pW + 2 * CH * CH, pXT, pV, CH, NALL, CH, CH, CH, NALL, 0, 0, 0, bv, nullptr, 1.f);

    // S_b = QT_b * KT_b^T * C^-0.5  (fp32)
    gemm_kernel<2><<<dim3(HWDIM / 128, HWDIM / 128, BATCH), 256>>>(
        pQT, pKT, pS, HWDIM, HWDIM, CH, CH, CH, HWDIM,
        (size_t)HWDIM * CH, (size_t)HWDIM * CH, (size_t)HWDIM * HWDIM,
        nullptr, nullptr, 0.04419417382415922f);

    // softmax rows -> P (bf16)
    softmax_kernel<<<BATCH * HWDIM, 256>>>(pS, pP);

    // HT_b = P_b * V_b^T   -> [b*HW+s][c]
    gemm_kernel<0><<<dim3(CH / 128, HWDIM / 128, BATCH), 256>>>(
        pP, pV, pHT, HWDIM, CH, HWDIM, HWDIM, NALL, CH,
        (size_t)HWDIM * HWDIM, (size_t)HWDIM, (size_t)HWDIM * CH,
        nullptr, nullptr, 1.f);

    // O = Wo * HT^T + bo + x  -> final [B][C][H][W]
    gemm_kernel<3><<<dim3(NALL / 128, CH / 128, 1), 256>>>(
        pW + 3 * CH * CH, pHT, out, CH, NALL, CH, CH, CH, 0,
        0, 0, 0, bo, x, 1.f);
}